// round 9
// baseline (speedup 1.0000x reference)
#include <cuda_runtime.h>
#include <cstdint>

#define DD 32
#define HH 64
#define NB 4096
#define EPSF 1e-10f
#define BSTRIDE 33

// Scratch (allocation-free rule: __device__ globals)
__device__ float g_V[(size_t)NB * DD * HH];   // [r][i][h]  33.5 MB
__device__ float g_CA[NB * HH];               // [r][h]

typedef unsigned long long u64;

__device__ __forceinline__ u64 fma2(u64 a, u64 b, u64 c) {
    u64 d; asm("fma.rn.f32x2 %0, %1, %2, %3;" : "=l"(d) : "l"(a), "l"(b), "l"(c)); return d;
}
__device__ __forceinline__ u64 add2(u64 a, u64 b) {
    u64 d; asm("add.rn.f32x2 %0, %1, %2;" : "=l"(d) : "l"(a), "l"(b)); return d;
}
__device__ __forceinline__ u64 pack2(float lo, float hi) {
    u64 d; asm("mov.b64 %0, {%1, %2};" : "=l"(d) : "f"(lo), "f"(hi)); return d;
}
__device__ __forceinline__ void unpack2(u64 a, float& lo, float& hi) {
    asm("mov.b64 {%0, %1}, %2;" : "=f"(lo), "=f"(hi) : "l"(a));
}
__device__ __forceinline__ float tanh_approx(float x) {
    float y; asm("tanh.approx.f32 %0, %1;" : "=f"(y) : "f"(x)); return y;
}

// ---------------------------------------------------------------------------
// Kernel A: per-candidate precompute.
//   grid (128 r-tiles, 17), 128 threads.
//   nt<16 : V[r,i,h] = W1[(32+i),h] + sum_j c[r,j] * W1[64+i*32+j, h]
//   nt==16: CA[r,h]  = b1[h] + sum_j c[r,j] * W1[j, h]
// ---------------------------------------------------------------------------
__global__ void __launch_bounds__(128) precompute_V(
    const float* __restrict__ cand,
    const float* __restrict__ W1,
    const float* __restrict__ b1)
{
    __shared__ __align__(16) float cs[32 * 32];
    int rt  = blockIdx.x;
    int nt  = blockIdx.y;
    int tid = threadIdx.x;

    const float4* csrc = (const float4*)(cand + (size_t)rt * 32 * DD);
    float4* cdst = (float4*)cs;
    cdst[tid]       = csrc[tid];
    cdst[tid + 128] = csrc[tid + 128];
    __syncthreads();

    if (nt < 16) {
        int n = nt * 128 + tid;          // n = i*64 + h
        int i = n >> 6, h = n & 63;
        const float* wbase = W1 + (size_t)(64 + i * 32) * HH + h;

        u64 acc2[32];
        #pragma unroll
        for (int rr = 0; rr < 32; rr++) acc2[rr] = 0ull;

        #pragma unroll
        for (int j4 = 0; j4 < 8; j4++) {
            float w0  = wbase[(j4 * 4 + 0) * HH];
            float w1v = wbase[(j4 * 4 + 1) * HH];
            float w2v = wbase[(j4 * 4 + 2) * HH];
            float w3v = wbase[(j4 * 4 + 3) * HH];
            u64 bp0 = pack2(w0, w1v);
            u64 bp1 = pack2(w2v, w3v);
            #pragma unroll
            for (int rr = 0; rr < 32; rr++) {
                ulonglong2 cc = *(const ulonglong2*)&cs[rr * 32 + j4 * 4];
                acc2[rr] = fma2(cc.x, bp0, acc2[rr]);
                acc2[rr] = fma2(cc.y, bp1, acc2[rr]);
            }
        }
        float wb = W1[(size_t)(32 + i) * HH + h];
        float* dst = g_V + (size_t)(rt * 32) * (DD * HH) + n;
        #pragma unroll
        for (int rr = 0; rr < 32; rr++) {
            float lo, hi; unpack2(acc2[rr], lo, hi);
            dst[(size_t)rr * (DD * HH)] = wb + lo + hi;
        }
    } else if (tid < 64) {
        int h = tid;
        float accs[32];
        float bb = b1[h];
        #pragma unroll
        for (int rr = 0; rr < 32; rr++) accs[rr] = bb;
        #pragma unroll 4
        for (int j = 0; j < 32; j++) {
            float wv = W1[(size_t)j * HH + h];
            #pragma unroll
            for (int rr = 0; rr < 32; rr++)
                accs[rr] = fmaf(cs[rr * 32 + j], wv, accs[rr]);
        }
        float* dst = g_CA + rt * 32 * HH + h;
        #pragma unroll
        for (int rr = 0; rr < 32; rr++) dst[rr * HH] = accs[rr];
    }
}

// ---------------------------------------------------------------------------
// Kernel B: 128 threads / block, 1 block per candidate.
// Tile = 64 rows. Warp pair p=wid>>1 owns rows [p*32, p*32+32); half=wid&1
// owns h range [half*32, half*32+32). Per-thread x2 = 16 u64 only.
// One-pass moments + tanh sigmoid. Cross-half combine via smem.
// ---------------------------------------------------------------------------
__global__ void __launch_bounds__(128, 6) attn_main(
    const float* __restrict__ behavior,
    const int*   __restrict__ row_ids,
    int T,
    const float* __restrict__ alpha,
    const float* __restrict__ W2,
    const float* __restrict__ b2,
    float* __restrict__ out)
{
    __shared__ __align__(16) float Vs[DD * HH];     // 8 KB
    __shared__ float bs[64 * BSTRIDE];              // 8.25 KB
    __shared__ __align__(16) float cas[HH];
    __shared__ __align__(16) float As[HH];          // 0.5*(1+alpha)
    __shared__ __align__(16) float Bsh[HH];         // 0.5*(1-alpha)
    __shared__ __align__(16) float w2s[HH];
    __shared__ float red1[2][64];                   // sum x      [half][row]
    __shared__ float red2[2][64];                   // sum x^2
    __shared__ float redw[2][64];                   // partial w
    __shared__ float partial[4][DD];
    __shared__ int   seg[2];

    int r    = blockIdx.x;
    int tid  = threadIdx.x;
    int lane = tid & 31;
    int wid  = tid >> 5;
    int pair = wid >> 1;        // 0/1 : row group
    int half = wid & 1;         // 0/1 : h group
    int row  = pair * 32 + lane;

    // stage V[r] (512 float4, 4 per thread), params
    {
        const float4* src = (const float4*)(g_V + (size_t)r * (DD * HH));
        float4* dst = (float4*)Vs;
        #pragma unroll
        for (int k = 0; k < 4; k++) dst[k * 128 + tid] = src[k * 128 + tid];
        if (tid < 64) {
            cas[tid] = g_CA[r * HH + tid];
            float al = alpha[tid];
            As[tid]  = 0.5f * (1.0f + al);
            Bsh[tid] = 0.5f * (1.0f - al);
            w2s[tid] = W2[tid];
        }
    }
    if (tid < 2) {
        int target = r + tid;
        int lo = 0, hi = T;
        while (lo < hi) {
            int mid = (lo + hi) >> 1;
            if (row_ids[mid] < target) lo = mid + 1; else hi = mid;
        }
        seg[tid] = lo;
    }
    float b2v = b2[0];
    __syncthreads();

    int start = seg[0];
    int end   = seg[1];

    float accd = 0.f;   // lane owns output dim d = lane; warp owns 16-row slices

    for (int base = start; base < end; base += 64) {
        int nrows = end - base; if (nrows > 64) nrows = 64;

        // cooperative load of tile (zero-fill tail so inactive rows are benign)
        {
            const float4* gsrc = (const float4*)(behavior + (size_t)base * DD);
            int n4 = nrows * 8;
            for (int idx = tid; idx < n4; idx += 128) {
                float4 v = gsrc[idx];
                float* d = &bs[(idx >> 3) * BSTRIDE + ((idx & 7) << 2)];
                d[0] = v.x; d[1] = v.y; d[2] = v.z; d[3] = v.w;
            }
            for (int idx = n4 + tid; idx < 512; idx += 128) {
                float* d = &bs[(idx >> 3) * BSTRIDE + ((idx & 7) << 2)];
                d[0] = 0.f; d[1] = 0.f; d[2] = 0.f; d[3] = 0.f;
            }
        }
        __syncthreads();

        // ---- matvec over this thread's 32 h ----
        const float* brow = &bs[row * BSTRIDE];
        u64 x2[16];
        {
            const ulonglong2* cp = (const ulonglong2*)&cas[half * 32];
            #pragma unroll
            for (int pp = 0; pp < 8; pp++) {
                ulonglong2 v = cp[pp];
                x2[2*pp] = v.x; x2[2*pp+1] = v.y;
            }
        }
        #pragma unroll
        for (int i = 0; i < DD; i++) {
            float bi = brow[i];
            u64 bb = pack2(bi, bi);
            const ulonglong2* vp = (const ulonglong2*)&Vs[i * HH + half * 32];
            #pragma unroll
            for (int pp = 0; pp < 8; pp++) {
                ulonglong2 v = vp[pp];
                x2[2*pp]   = fma2(v.x, bb, x2[2*pp]);
                x2[2*pp+1] = fma2(v.y, bb, x2[2*pp+1]);
            }
        }

        // ---- one-pass moments over this half ----
        u64 sa = x2[0], sb = x2[1], sc = x2[2], sd = x2[3];
        u64 qa = fma2(x2[0], x2[0], 0ull), qb = fma2(x2[1], x2[1], 0ull);
        u64 qc = fma2(x2[2], x2[2], 0ull), qd = fma2(x2[3], x2[3], 0ull);
        #pragma unroll
        for (int p = 4; p < 16; p += 4) {
            sa = add2(sa, x2[p]);   sb = add2(sb, x2[p+1]);
            sc = add2(sc, x2[p+2]); sd = add2(sd, x2[p+3]);
            qa = fma2(x2[p],   x2[p],   qa); qb = fma2(x2[p+1], x2[p+1], qb);
            qc = fma2(x2[p+2], x2[p+2], qc); qd = fma2(x2[p+3], x2[p+3], qd);
        }
        u64 st = add2(add2(sa, sb), add2(sc, sd));
        u64 qt = add2(add2(qa, qb), add2(qc, qd));
        float slo, shi, qlo, qhi;
        unpack2(st, slo, shi); unpack2(qt, qlo, qhi);
        red1[half][row] = slo + shi;
        red2[half][row] = qlo + qhi;
        __syncthreads();

        float mean = (red1[0][row] + red1[1][row]) * (1.0f / 64.0f);
        float msq  = (red2[0][row] + red2[1][row]) * (1.0f / 64.0f);
        float var  = msq - mean * mean + EPSF;
        float stdv = sqrtf(var);
        float rinv = __fdividef(1.0f, stdv + EPSF);
        float hr = 0.5f * rinv;
        float hm = -mean * hr;   // u = x*hr + hm ;  p = 0.5 + 0.5*tanh(u)

        // ---- activation + W2 partial dot over this half ----
        float w = 0.f;
        #pragma unroll
        for (int pp = 0; pp < 8; pp++) {
            int hb = half * 32 + pp * 4;
            float4 A4  = *(const float4*)&As[hb];
            float4 B4  = *(const float4*)&Bsh[hb];
            float4 w24 = *(const float4*)&w2s[hb];
            float xa, xb_, xc, xd;
            unpack2(x2[2*pp],   xa, xb_);
            unpack2(x2[2*pp+1], xc, xd);
            { float t = tanh_approx(fmaf(xa,  hr, hm)); w = fmaf(xa  * fmaf(B4.x, t, A4.x), w24.x, w); }
            { float t = tanh_approx(fmaf(xb_, hr, hm)); w = fmaf(xb_ * fmaf(B4.y, t, A4.y), w24.y, w); }
            { float t = tanh_approx(fmaf(xc,  hr, hm)); w = fmaf(xc  * fmaf(B4.z, t, A4.z), w24.z, w); }
            { float t = tanh_approx(fmaf(xd,  hr, hm)); w = fmaf(xd  * fmaf(B4.w, t, A4.w), w24.w, w); }
        }
        redw[half][row] = w;
        __syncthreads();

        // ---- segment-sum epilogue: warp wid handles rows [wid*16, wid*16+16) ----
        int r0 = wid * 16;
        int r1 = r0 + 16; if (r1 > nrows) r1 = nrows;
        for (int rr = r0; rr < r1; rr++) {
            float wv = redw[0][rr] + redw[1][rr] + b2v;
            accd = fmaf(bs[rr * BSTRIDE + lane], wv, accd);
        }
        __syncthreads();   // bs/red reuse next tile
    }

    partial[wid][lane] = accd;
    __syncthreads();
    if (wid == 0)
        out[(size_t)r * DD + lane] =
            partial[0][lane] + partial[1][lane] + partial[2][lane] + partial[3][lane];
}

// ---------------------------------------------------------------------------
extern "C" void kernel_launch(void* const* d_in, const int* in_sizes, int n_in,
                              void* d_out, int out_size) {
    const float* cand    = (const float*)d_in[0];
    const float* behav   = (const float*)d_in[1];
    const int*   row_ids = (const int*)  d_in[2];
    const float* W1      = (const float*)d_in[3];
    const float* b1      = (const float*)d_in[4];
    const float* alphaP  = (const float*)d_in[5];
    const float* W2      = (const float*)d_in[6];
    const float* b2      = (const float*)d_in[7];
    float* out = (float*)d_out;
    int T = in_sizes[2];

    precompute_V<<<dim3(128, 17), 128>>>(cand, W1, b1);
    attn_main<<<NB, 128>>>(behav, row_ids, T, alphaP, W2, b2, out);
}

// round 11
// speedup vs baseline: 1.1317x; 1.1317x over previous
#include <cuda_runtime.h>
#include <cstdint>

#define DD 32
#define HH 64
#define NB 4096
#define EPSF 1e-10f
#define BSTRIDE 33

// Scratch (allocation-free rule: __device__ globals)
__device__ float g_V[(size_t)NB * DD * HH];   // [r][i][h]  33.5 MB
__device__ float g_CA[NB * HH];               // [r][h]
__device__ int   g_off[NB + 1];

typedef unsigned long long u64;

__device__ __forceinline__ u64 fma2(u64 a, u64 b, u64 c) {
    u64 d; asm("fma.rn.f32x2 %0, %1, %2, %3;" : "=l"(d) : "l"(a), "l"(b), "l"(c)); return d;
}
__device__ __forceinline__ u64 add2(u64 a, u64 b) {
    u64 d; asm("add.rn.f32x2 %0, %1, %2;" : "=l"(d) : "l"(a), "l"(b)); return d;
}
__device__ __forceinline__ u64 pack2(float lo, float hi) {
    u64 d; asm("mov.b64 %0, {%1, %2};" : "=l"(d) : "f"(lo), "f"(hi)); return d;
}
__device__ __forceinline__ void unpack2(u64 a, float& lo, float& hi) {
    asm("mov.b64 {%0, %1}, %2;" : "=f"(lo), "=f"(hi) : "l"(a));
}
__device__ __forceinline__ float tanh_approx(float x) {
    float y; asm("tanh.approx.f32 %0, %1;" : "=f"(y) : "f"(x)); return y;
}

// ---------------------------------------------------------------------------
// Kernel C: segment offsets from sorted row_ids (parallel scatter).
// g_off[q] = lower_bound(row_ids, q)
// ---------------------------------------------------------------------------
__global__ void build_offsets(const int* __restrict__ row_ids, int T) {
    int t = blockIdx.x * blockDim.x + threadIdx.x;
    if (t >= T) return;
    int r  = row_ids[t];
    int rp = (t == 0) ? -1 : row_ids[t - 1];
    for (int q = rp + 1; q <= r; q++) g_off[q] = t;
    if (t == T - 1) {
        for (int q = r + 1; q <= NB; q++) g_off[q] = T;
    }
}

// ---------------------------------------------------------------------------
// Kernel A: per-candidate precompute.
//   grid (128 r-tiles, 17), 128 threads.
//   nt<16 : V[r,i,h] = W1[(32+i),h] + sum_j c[r,j] * W1[64+i*32+j, h]
//   nt==16: CA[r,h]  = b1[h] + sum_j c[r,j] * W1[j, h]
// ---------------------------------------------------------------------------
__global__ void __launch_bounds__(128) precompute_V(
    const float* __restrict__ cand,
    const float* __restrict__ W1,
    const float* __restrict__ b1)
{
    __shared__ __align__(16) float cs[32 * 32];
    int rt  = blockIdx.x;
    int nt  = blockIdx.y;
    int tid = threadIdx.x;

    const float4* csrc = (const float4*)(cand + (size_t)rt * 32 * DD);
    float4* cdst = (float4*)cs;
    cdst[tid]       = csrc[tid];
    cdst[tid + 128] = csrc[tid + 128];
    __syncthreads();

    if (nt < 16) {
        int n = nt * 128 + tid;          // n = i*64 + h
        int i = n >> 6, h = n & 63;
        const float* wbase = W1 + (size_t)(64 + i * 32) * HH + h;

        u64 acc2[32];
        #pragma unroll
        for (int rr = 0; rr < 32; rr++) acc2[rr] = 0ull;

        #pragma unroll
        for (int j4 = 0; j4 < 8; j4++) {
            float w0  = wbase[(j4 * 4 + 0) * HH];
            float w1v = wbase[(j4 * 4 + 1) * HH];
            float w2v = wbase[(j4 * 4 + 2) * HH];
            float w3v = wbase[(j4 * 4 + 3) * HH];
            u64 bp0 = pack2(w0, w1v);
            u64 bp1 = pack2(w2v, w3v);
            #pragma unroll
            for (int rr = 0; rr < 32; rr++) {
                ulonglong2 cc = *(const ulonglong2*)&cs[rr * 32 + j4 * 4];
                acc2[rr] = fma2(cc.x, bp0, acc2[rr]);
                acc2[rr] = fma2(cc.y, bp1, acc2[rr]);
            }
        }
        float wb = W1[(size_t)(32 + i) * HH + h];
        float* dst = g_V + (size_t)(rt * 32) * (DD * HH) + n;
        #pragma unroll
        for (int rr = 0; rr < 32; rr++) {
            float lo, hi; unpack2(acc2[rr], lo, hi);
            dst[(size_t)rr * (DD * HH)] = wb + lo + hi;
        }
    } else if (tid < 64) {
        int h = tid;
        float accs[32];
        float bb = b1[h];
        #pragma unroll
        for (int rr = 0; rr < 32; rr++) accs[rr] = bb;
        #pragma unroll 4
        for (int j = 0; j < 32; j++) {
            float wv = W1[(size_t)j * HH + h];
            #pragma unroll
            for (int rr = 0; rr < 32; rr++)
                accs[rr] = fmaf(cs[rr * 32 + j], wv, accs[rr]);
        }
        float* dst = g_CA + rt * 32 * HH + h;
        #pragma unroll
        for (int rr = 0; rr < 32; rr++) dst[rr * HH] = accs[rr];
    }
}

// ---------------------------------------------------------------------------
// Kernel B: 128 threads / block, 1 block per candidate.
// g_off lookup (no serial search). First tile load merged into setup.
// ---------------------------------------------------------------------------
__global__ void __launch_bounds__(128, 7) attn_main(
    const float* __restrict__ behavior,
    const float* __restrict__ alpha,
    const float* __restrict__ W2,
    const float* __restrict__ b2,
    float* __restrict__ out)
{
    __shared__ __align__(16) float Vs[DD * HH];     // 8 KB
    __shared__ float bs[64 * BSTRIDE];              // 8.25 KB
    __shared__ __align__(16) float cas[HH];
    __shared__ __align__(16) float As[HH];          // 0.5*(1+alpha)
    __shared__ __align__(16) float Bsh[HH];         // 0.5*(1-alpha)
    __shared__ __align__(16) float w2s[HH];
    __shared__ float red1[2][64];                   // sum x      [half][row]
    __shared__ float red2[2][64];                   // sum x^2
    __shared__ float redw[2][64];                   // partial w
    __shared__ float partial[4][DD];

    int r    = blockIdx.x;
    int tid  = threadIdx.x;
    int lane = tid & 31;
    int wid  = tid >> 5;
    int pair = wid >> 1;        // 0/1 : row group
    int half = wid & 1;         // 0/1 : h group
    int row  = pair * 32 + lane;

    // issue segment-bound loads FIRST so latency overlaps staging below
    int start = __ldg(&g_off[r]);
    int end   = __ldg(&g_off[r + 1]);
    float b2v = b2[0];

    // stage V[r] (512 float4, 4 per thread), params
    {
        const float4* src = (const float4*)(g_V + (size_t)r * (DD * HH));
        float4* dst = (float4*)Vs;
        #pragma unroll
        for (int k = 0; k < 4; k++) dst[k * 128 + tid] = src[k * 128 + tid];
        if (tid < 64) {
            cas[tid] = g_CA[r * HH + tid];
            float al = alpha[tid];
            As[tid]  = 0.5f * (1.0f + al);
            Bsh[tid] = 0.5f * (1.0f - al);
            w2s[tid] = W2[tid];
        }
    }

    // first behavior tile load merged into setup (common case: only tile)
    {
        int nrows0 = end - start; if (nrows0 > 64) nrows0 = 64;
        if (nrows0 < 0) nrows0 = 0;
        const float4* gsrc = (const float4*)(behavior + (size_t)start * DD);
        int n4 = nrows0 * 8;
        for (int idx = tid; idx < n4; idx += 128) {
            float4 v = gsrc[idx];
            float* d = &bs[(idx >> 3) * BSTRIDE + ((idx & 7) << 2)];
            d[0] = v.x; d[1] = v.y; d[2] = v.z; d[3] = v.w;
        }
        for (int idx = n4 + tid; idx < 512; idx += 128) {
            float* d = &bs[(idx >> 3) * BSTRIDE + ((idx & 7) << 2)];
            d[0] = 0.f; d[1] = 0.f; d[2] = 0.f; d[3] = 0.f;
        }
    }
    __syncthreads();

    float accd = 0.f;   // lane owns output dim d = lane; warp owns 16-row slices

    for (int base = start; base < end; base += 64) {
        int nrows = end - base; if (nrows > 64) nrows = 64;

        if (base != start) {
            // load this tile (not the first)
            const float4* gsrc = (const float4*)(behavior + (size_t)base * DD);
            int n4 = nrows * 8;
            for (int idx = tid; idx < n4; idx += 128) {
                float4 v = gsrc[idx];
                float* d = &bs[(idx >> 3) * BSTRIDE + ((idx & 7) << 2)];
                d[0] = v.x; d[1] = v.y; d[2] = v.z; d[3] = v.w;
            }
            for (int idx = n4 + tid; idx < 512; idx += 128) {
                float* d = &bs[(idx >> 3) * BSTRIDE + ((idx & 7) << 2)];
                d[0] = 0.f; d[1] = 0.f; d[2] = 0.f; d[3] = 0.f;
            }
            __syncthreads();
        }

        // ---- matvec over this thread's 32 h ----
        const float* brow = &bs[row * BSTRIDE];
        u64 x2[16];
        {
            const ulonglong2* cp = (const ulonglong2*)&cas[half * 32];
            #pragma unroll
            for (int pp = 0; pp < 8; pp++) {
                ulonglong2 v = cp[pp];
                x2[2*pp] = v.x; x2[2*pp+1] = v.y;
            }
        }
        #pragma unroll
        for (int i = 0; i < DD; i++) {
            float bi = brow[i];
            u64 bb = pack2(bi, bi);
            const ulonglong2* vp = (const ulonglong2*)&Vs[i * HH + half * 32];
            #pragma unroll
            for (int pp = 0; pp < 8; pp++) {
                ulonglong2 v = vp[pp];
                x2[2*pp]   = fma2(v.x, bb, x2[2*pp]);
                x2[2*pp+1] = fma2(v.y, bb, x2[2*pp+1]);
            }
        }

        // ---- one-pass moments over this half ----
        u64 sa = x2[0], sb = x2[1], sc = x2[2], sd = x2[3];
        u64 qa = fma2(x2[0], x2[0], 0ull), qb = fma2(x2[1], x2[1], 0ull);
        u64 qc = fma2(x2[2], x2[2], 0ull), qd = fma2(x2[3], x2[3], 0ull);
        #pragma unroll
        for (int p = 4; p < 16; p += 4) {
            sa = add2(sa, x2[p]);   sb = add2(sb, x2[p+1]);
            sc = add2(sc, x2[p+2]); sd = add2(sd, x2[p+3]);
            qa = fma2(x2[p],   x2[p],   qa); qb = fma2(x2[p+1], x2[p+1], qb);
            qc = fma2(x2[p+2], x2[p+2], qc); qd = fma2(x2[p+3], x2[p+3], qd);
        }
        u64 st = add2(add2(sa, sb), add2(sc, sd));
        u64 qt = add2(add2(qa, qb), add2(qc, qd));
        float slo, shi, qlo, qhi;
        unpack2(st, slo, shi); unpack2(qt, qlo, qhi);
        red1[half][row] = slo + shi;
        red2[half][row] = qlo + qhi;
        __syncthreads();

        float mean = (red1[0][row] + red1[1][row]) * (1.0f / 64.0f);
        float msq  = (red2[0][row] + red2[1][row]) * (1.0f / 64.0f);
        float var  = msq - mean * mean + EPSF;
        float stdv = sqrtf(var);
        float rinv = __fdividef(1.0f, stdv + EPSF);
        float hr = 0.5f * rinv;
        float hm = -mean * hr;   // u = x*hr + hm ;  p = 0.5 + 0.5*tanh(u)

        // ---- activation + W2 partial dot over this half ----
        float w = 0.f;
        #pragma unroll
        for (int pp = 0; pp < 8; pp++) {
            int hb = half * 32 + pp * 4;
            float4 A4  = *(const float4*)&As[hb];
            float4 B4  = *(const float4*)&Bsh[hb];
            float4 w24 = *(const float4*)&w2s[hb];
            float xa, xb_, xc, xd;
            unpack2(x2[2*pp],   xa, xb_);
            unpack2(x2[2*pp+1], xc, xd);
            { float t = tanh_approx(fmaf(xa,  hr, hm)); w = fmaf(xa  * fmaf(B4.x, t, A4.x), w24.x, w); }
            { float t = tanh_approx(fmaf(xb_, hr, hm)); w = fmaf(xb_ * fmaf(B4.y, t, A4.y), w24.y, w); }
            { float t = tanh_approx(fmaf(xc,  hr, hm)); w = fmaf(xc  * fmaf(B4.z, t, A4.z), w24.z, w); }
            { float t = tanh_approx(fmaf(xd,  hr, hm)); w = fmaf(xd  * fmaf(B4.w, t, A4.w), w24.w, w); }
        }
        redw[half][row] = w;
        __syncthreads();

        // ---- segment-sum epilogue: warp wid handles rows [wid*16, wid*16+16) ----
        int r0 = wid * 16;
        int r1 = r0 + 16; if (r1 > nrows) r1 = nrows;
        for (int rr = r0; rr < r1; rr++) {
            float wv = redw[0][rr] + redw[1][rr] + b2v;
            accd = fmaf(bs[rr * BSTRIDE + lane], wv, accd);
        }
        __syncthreads();   // bs/red reuse next tile
    }

    partial[wid][lane] = accd;
    __syncthreads();
    if (wid == 0)
        out[(size_t)r * DD + lane] =
            partial[0][lane] + partial[1][lane] + partial[2][lane] + partial[3][lane];
}

// ---------------------------------------------------------------------------
extern "C" void kernel_launch(void* const* d_in, const int* in_sizes, int n_in,
                              void* d_out, int out_size) {
    const float* cand    = (const float*)d_in[0];
    const float* behav   = (const float*)d_in[1];
    const int*   row_ids = (const int*)  d_in[2];
    const float* W1      = (const float*)d_in[3];
    const float* b1      = (const float*)d_in[4];
    const float* alphaP  = (const float*)d_in[5];
    const float* W2      = (const float*)d_in[6];
    const float* b2      = (const float*)d_in[7];
    float* out = (float*)d_out;
    int T = in_sizes[2];

    build_offsets<<<(T + 255) / 256, 256>>>(row_ids, T);
    precompute_V<<<dim3(128, 17), 128>>>(cand, W1, b1);
    attn_main<<<NB, 128>>>(behav, alphaP, W2, b2, out);
}